// round 12
// baseline (speedup 1.0000x reference)
#include <cuda_runtime.h>
#include <math.h>

// ---------------------------------------------------------------------------
// Problem constants
// ---------------------------------------------------------------------------
#define FEAT   72
#define RSHD   25
#define RTOT   1216
#define NBASIS 10
#define HID    100
#define TE     16       // edges per block
#define NTHR   256

// 19 (lo,li,lf) combos, i-major / j-minor / lf ascending
__device__ __constant__ int c3_lo[19]  = {0,0,0,1,1,1,1,1,1,1,2,2,2,2,2,2,2,2,2};
__device__ __constant__ int c3_li[19]  = {0,1,2,0,1,1,1,2,2,2,0,1,1,1,2,2,2,2,2};
__device__ __constant__ int c3_lf[19]  = {0,1,2,1,0,1,2,1,2,3,2,1,2,3,0,1,2,3,4};
__device__ __constant__ int c3_off[19] = {0,1,10,35,44,53,80,125,170,245,350,375,420,495,600,625,700,825,1000};

__device__ float g_C3[1225];

// ---------------------------------------------------------------------------
// Init kernel: compute real-basis Wigner 3j coupling tensors (double precision)
// ---------------------------------------------------------------------------
__device__ double dfac(int n) {
    double r = 1.0;
    for (int i = 2; i <= n; i++) r *= (double)i;
    return r;
}

__device__ double w3j_entry(int j1, int j2, int j3, int m1, int m2, int m3) {
    if (m1 + m2 + m3 != 0) return 0.0;
    int t1 = j2 - m1 - j3, t2 = j1 + m2 - j3;
    int kmin = 0; if (t1 > kmin) kmin = t1; if (t2 > kmin) kmin = t2;
    int kmax = j1 + j2 - j3;
    if (j1 - m1 < kmax) kmax = j1 - m1;
    if (j2 + m2 < kmax) kmax = j2 + m2;
    double s = 0.0;
    for (int k = kmin; k <= kmax; k++) {
        double d = dfac(k) * dfac(k - t1) * dfac(k - t2) * dfac(j1 + j2 - j3 - k)
                 * dfac(j1 - m1 - k) * dfac(j2 + m2 - k);
        s += ((k & 1) ? -1.0 : 1.0) / d;
    }
    int pw = j1 - j2 - m3;
    double sign = (pw & 1) ? -1.0 : 1.0;
    double pref = sign * sqrt(
        dfac(j1 + j2 - j3) * dfac(j1 - j2 + j3) * dfac(-j1 + j2 + j3) / dfac(j1 + j2 + j3 + 1)
        * dfac(j1 + m1) * dfac(j1 - m1) * dfac(j2 + m2) * dfac(j2 - m2)
        * dfac(j3 + m3) * dfac(j3 - m3));
    return pref * s;
}

__device__ void buildU(int l, double Ur[9][9], double Ui[9][9]) {
    for (int a = 0; a < 9; a++)
        for (int b = 0; b < 9; b++) { Ur[a][b] = 0.0; Ui[a][b] = 0.0; }
    Ur[l][l] = 1.0;
    const double s = 0.70710678118654752440;
    for (int m = 1; m <= l; m++) {
        Ur[l + m][l + m] = (m & 1) ? -s : s;   // (-1)^m / sqrt2
        Ur[l + m][l - m] = s;
        Ui[l - m][l - m] = s;                  // i / sqrt2
        Ui[l - m][l + m] = (m & 1) ? s : -s;   // -i(-1)^m / sqrt2
    }
}

__global__ void init_c3_kernel() {
    const int ci = blockIdx.x;
    const int lo = c3_lo[ci], li = c3_li[ci], lf = c3_lf[ci];
    const int n1 = 2 * lo + 1, n2 = 2 * li + 1, n3 = 2 * lf + 1;
    const int tid = threadIdx.x;

    __shared__ double wtab[25];
    __shared__ double Tre[225], Tim[225];
    __shared__ int    sUseReal;
    __shared__ double sInv;

    if (tid < n1 * n2) {
        int m1 = tid / n2 - lo;
        int m2 = tid % n2 - li;
        int m3 = -m1 - m2;
        double w = 0.0;
        if (m3 >= -lf && m3 <= lf) w = w3j_entry(lo, li, lf, m1, m2, m3);
        wtab[tid] = w;
    }
    __syncthreads();

    double U1r[9][9], U1i[9][9], U2r[9][9], U2i[9][9], U3r[9][9], U3i[9][9];
    buildU(lo, U1r, U1i);
    buildU(li, U2r, U2i);
    buildU(lf, U3r, U3i);

    const int ntot = n1 * n2 * n3;
    for (int out = tid; out < ntot; out += blockDim.x) {
        int a = out / (n2 * n3);
        int b = (out / n3) % n2;
        int c = out % n3;
        double sre = 0.0, sim = 0.0;
        for (int m = 0; m < n1; m++) {
            for (int n = 0; n < n2; n++) {
                double w = wtab[m * n2 + n];
                if (w == 0.0) continue;
                int m3 = -(m - lo) - (n - li);
                int p = m3 + lf;
                double ar = U1r[a][m], ai = U1i[a][m];
                double br = U2r[b][n], bi = U2i[b][n];
                double pr = ar * br - ai * bi;
                double pi = ar * bi + ai * br;
                double cr = U3r[c][p], ci3 = U3i[c][p];
                double qr = pr * cr - pi * ci3;
                double qi = pr * ci3 + pi * cr;
                sre += w * qr;
                sim += w * qi;
            }
        }
        Tre[out] = sre;
        Tim[out] = sim;
    }
    __syncthreads();

    if (tid == 0) {
        double nr = 0.0, ni = 0.0;
        for (int t = 0; t < ntot; t++) { nr += Tre[t] * Tre[t]; ni += Tim[t] * Tim[t]; }
        int ur = (nr >= ni) ? 1 : 0;
        double nn = sqrt(ur ? nr : ni);
        sUseReal = ur;
        sInv = (nn > 0.0) ? (1.0 / nn) : 1.0;
    }
    __syncthreads();

    const int base = c3_off[ci];
    for (int out = tid; out < ntot; out += blockDim.x) {
        double v = (sUseReal ? Tre[out] : Tim[out]) * sInv;
        g_C3[base + out] = (float)v;
    }
}

// ---------------------------------------------------------------------------
// Zero the output buffer (poisoned to 0xAA by harness)
// ---------------------------------------------------------------------------
__global__ void zero_kernel(float* __restrict__ out, int n) {
    int i = blockIdx.x * blockDim.x + threadIdx.x;
    if (i < n) out[i] = 0.0f;
}

// ---------------------------------------------------------------------------
// Fused edge kernel: radial MLP + tensor message + atomic scatter
// ---------------------------------------------------------------------------
__device__ __forceinline__ float swishf(float x) {
    return 1.679177f * x / (1.0f + expf(-x));
}

__global__ __launch_bounds__(NTHR) void edge_kernel(
    const float* __restrict__ features,
    const int*   __restrict__ eidx,     // [2, E]
    const float* __restrict__ radii,
    const float* __restrict__ rsh,      // [E, 25]
    const float* __restrict__ W0,       // [10, 100]
    const float* __restrict__ W1,       // [100, 100]
    const float* __restrict__ W2,       // [100, 100]
    const float* __restrict__ W3,       // [100, 1216]
    float* __restrict__ out,            // [N, 72]
    int E)
{
    __shared__ float sF[TE][FEAT];
    __shared__ float sRsh[TE][RSHD];
    __shared__ float sAcc[TE][FEAT];
    __shared__ float sHT[HID][17];      // hidden, k-major, padded
    __shared__ float sBT[NBASIS][17];   // gaussian basis, k-major, padded
    __shared__ float sR[TE][320];       // current (i,j) block of R
    __shared__ float sC3[1225];
    __shared__ int   sSrc[TE], sDst[TE];
    __shared__ float sRad[TE];

    const int tid = threadIdx.x;
    const int e0  = blockIdx.x * TE;
    const int nE  = min(TE, E - e0);
    if (nE <= 0) return;

    for (int i = tid; i < 1225; i += NTHR) sC3[i] = g_C3[i];
    if (tid < TE) {
        int e = e0 + min(tid, nE - 1);
        sSrc[tid] = eidx[e];
        sDst[tid] = eidx[E + e];
        sRad[tid] = radii[e];
    }
    __syncthreads();

    for (int f = tid; f < TE * FEAT; f += NTHR) {
        int e = f / FEAT, c = f % FEAT;
        sF[e][c] = features[sSrc[e] * FEAT + c];
        sAcc[e][c] = 0.0f;
    }
    for (int f = tid; f < TE * RSHD; f += NTHR) {
        int e = f / RSHD, c = f % RSHD;
        int ge = e0 + min(e, nE - 1);
        sRsh[e][c] = rsh[ge * RSHD + c];
    }
    if (tid < TE * NBASIS) {
        int e = tid / NBASIS, b = tid % NBASIS;
        float ctr = 0.7f + (float)b * (2.5f / 9.0f);
        float d = (sRad[e] - ctr) * (9.0f / 2.5f);
        sBT[b][e] = expf(-d * d);
    }
    __syncthreads();

    // ---------------- radial MLP (3 swish layers) ----------------
    {
        const int u = tid & 127;
        const int eh = tid >> 7;        // 0 or 1 -> edges eh*8 .. eh*8+7
        float a[8];

        // layer 0: 10 -> 100, scale 1/sqrt(10)
        if (u < HID) {
            #pragma unroll
            for (int ee = 0; ee < 8; ee++) a[ee] = 0.0f;
            #pragma unroll
            for (int k = 0; k < NBASIS; k++) {
                float w = W0[k * HID + u];
                #pragma unroll
                for (int ee = 0; ee < 8; ee++) a[ee] += sBT[k][eh * 8 + ee] * w;
            }
            #pragma unroll
            for (int ee = 0; ee < 8; ee++)
                sHT[u][eh * 8 + ee] = swishf(a[ee] * 0.31622776601683794f);
        }
        __syncthreads();

        // layer 1: 100 -> 100, scale 0.1
        if (u < HID) {
            #pragma unroll
            for (int ee = 0; ee < 8; ee++) a[ee] = 0.0f;
            #pragma unroll 4
            for (int k = 0; k < HID; k++) {
                float w = W1[k * HID + u];
                #pragma unroll
                for (int ee = 0; ee < 8; ee++) a[ee] += sHT[k][eh * 8 + ee] * w;
            }
        }
        __syncthreads();
        if (u < HID) {
            #pragma unroll
            for (int ee = 0; ee < 8; ee++)
                sHT[u][eh * 8 + ee] = swishf(a[ee] * 0.1f);
        }
        __syncthreads();

        // layer 2: 100 -> 100, scale 0.1
        if (u < HID) {
            #pragma unroll
            for (int ee = 0; ee < 8; ee++) a[ee] = 0.0f;
            #pragma unroll 4
            for (int k = 0; k < HID; k++) {
                float w = W2[k * HID + u];
                #pragma unroll
                for (int ee = 0; ee < 8; ee++) a[ee] += sHT[k][eh * 8 + ee] * w;
            }
        }
        __syncthreads();
        if (u < HID) {
            #pragma unroll
            for (int ee = 0; ee < 8; ee++)
                sHT[u][eh * 8 + ee] = swishf(a[ee] * 0.1f);
        }
        __syncthreads();
    }

    // ---------------- per-(lo,li) block: R-GEMM + message ----------------
    float NORMv[3];
    {
        const float num[3] = {24.0f, 56.0f, 72.0f};
        #pragma unroll
        for (int l = 0; l < 3; l++)
            NORMv[l] = sqrtf(12.566370614359172f * (float)(2 * l + 1) / num[l]);
    }

    const int colbase[9] = {0, 64, 128, 192, 256, 448, 640, 704, 896};
    const int p_lo[9]    = {0, 0, 0, 1, 1, 1, 2, 2, 2};
    const int p_li[9]    = {0, 1, 2, 0, 1, 2, 0, 1, 2};
    const int p_nlf[9]   = {1, 1, 1, 1, 3, 3, 1, 3, 5};
    const int p_cb[9]    = {0, 1, 2, 3, 4, 7, 10, 11, 14};
    const int foff[3]    = {0, 8, 32};
    const int c3offL[19] = {0,1,10,35,44,53,80,125,170,245,350,375,420,495,600,625,700,825,1000};

    const int ct = tid & 63;    // column lane within 64
    const int eg = tid >> 6;    // edge group (4 edges each)

    #pragma unroll
    for (int p = 0; p < 9; p++) {
        const int lo  = p_lo[p];
        const int li  = p_li[p];
        const int nlf = p_nlf[p];
        const int no  = 2 * lo + 1;
        const int ni  = 2 * li + 1;
        const int cb  = colbase[p];
        const int lfmin = (lo > li) ? lo - li : li - lo;

        // GEMM: R block [TE][64*nlf] = h2 @ W3[:, cb : cb+64*nlf] * 0.1
        float acc[5][4];
        #pragma unroll
        for (int cc = 0; cc < 5; cc++) {
            #pragma unroll
            for (int ee = 0; ee < 4; ee++) acc[cc][ee] = 0.0f;
        }
        #pragma unroll 2
        for (int k = 0; k < HID; k++) {
            float h0 = sHT[k][eg * 4 + 0];
            float h1 = sHT[k][eg * 4 + 1];
            float h2v = sHT[k][eg * 4 + 2];
            float h3 = sHT[k][eg * 4 + 3];
            const float* wrow = W3 + k * RTOT + cb + ct;
            #pragma unroll
            for (int cc = 0; cc < 5; cc++) {
                if (cc < nlf) {
                    float w = wrow[64 * cc];
                    acc[cc][0] += w * h0;
                    acc[cc][1] += w * h1;
                    acc[cc][2] += w * h2v;
                    acc[cc][3] += w * h3;
                }
            }
        }
        #pragma unroll
        for (int cc = 0; cc < 5; cc++) {
            if (cc < nlf) {
                #pragma unroll
                for (int ee = 0; ee < 4; ee++)
                    sR[eg * 4 + ee][ct + 64 * cc] = acc[cc][ee] * 0.1f;
            }
        }
        __syncthreads();

        // message: acc[e,u,o] += NORM * sum_{v,fi} Rb[u,v,fi] * sum_i' K[o,i']*F[v,i']
        const int nout = TE * 8 * no;
        for (int flat = tid; flat < nout; flat += NTHR) {
            int o = flat % no;
            int u = (flat / no) & 7;
            int e = flat / (no * 8);
            float aa = 0.0f;
            #pragma unroll
            for (int fi = 0; fi < 5; fi++) {
                if (fi < nlf) {
                    int lf = lfmin + fi;
                    int nf = 2 * lf + 1;
                    const float* C   = &sC3[c3offL[p_cb[p] + fi]];
                    const float* ysh = &sRsh[e][lf * lf];
                    float K[5];
                    #pragma unroll
                    for (int i2 = 0; i2 < 5; i2++) {
                        if (i2 < ni) {
                            float kk = 0.0f;
                            #pragma unroll
                            for (int mf = 0; mf < 9; mf++) {
                                if (mf < nf) kk += C[(o * ni + i2) * nf + mf] * ysh[mf];
                            }
                            K[i2] = kk;
                        }
                    }
                    const float* Fb = &sF[e][foff[li]];
                    const float* Rr = &sR[e][0];
                    #pragma unroll
                    for (int v = 0; v < 8; v++) {
                        float tv = 0.0f;
                        #pragma unroll
                        for (int i2 = 0; i2 < 5; i2++) {
                            if (i2 < ni) tv += K[i2] * Fb[v * ni + i2];
                        }
                        aa += Rr[(u * 8 + v) * nlf + fi] * tv;
                    }
                }
            }
            sAcc[e][foff[lo] + u * no + o] += NORMv[lo] * aa;
        }
        __syncthreads();
    }

    // ---------------- scatter-add ----------------
    for (int f = tid; f < nE * FEAT; f += NTHR) {
        int e = f / FEAT, c = f % FEAT;
        atomicAdd(&out[sDst[e] * FEAT + c], sAcc[e][c]);
    }
}

// ---------------------------------------------------------------------------
// Launch
// ---------------------------------------------------------------------------
extern "C" void kernel_launch(void* const* d_in, const int* in_sizes, int n_in,
                              void* d_out, int out_size) {
    const float* features = (const float*)d_in[0];
    const int*   eidx     = (const int*)  d_in[1];
    const float* radii    = (const float*)d_in[2];
    const float* rsh      = (const float*)d_in[3];
    const float* W0       = (const float*)d_in[4];
    const float* W1       = (const float*)d_in[5];
    const float* W2       = (const float*)d_in[6];
    const float* W3       = (const float*)d_in[7];
    float* out = (float*)d_out;

    const int E = in_sizes[2];

    init_c3_kernel<<<19, 128>>>();
    zero_kernel<<<(out_size + 511) / 512, 512>>>(out, out_size);
    const int nb = (E + TE - 1) / TE;
    edge_kernel<<<nb, NTHR>>>(features, eidx, radii, rsh, W0, W1, W2, W3, out, E);
}

// round 13
// speedup vs baseline: 1.4899x; 1.4899x over previous
#include <cuda_runtime.h>
#include <math.h>

// ---------------------------------------------------------------------------
// Problem constants
// ---------------------------------------------------------------------------
#define FEAT   72
#define RSHD   25
#define RTOT   1216
#define NBASIS 10
#define HID    100
#define TE     32       // edges per block
#define NTHR   256
#define SR_STR 324      // padded row stride for sR (kills bank conflicts)

// 19 (lo,li,lf) combos, lo-major / li / lf ascending
__device__ __constant__ int c3_lo[19]  = {0,0,0,1,1,1,1,1,1,1,2,2,2,2,2,2,2,2,2};
__device__ __constant__ int c3_li[19]  = {0,1,2,0,1,1,1,2,2,2,0,1,1,1,2,2,2,2,2};
__device__ __constant__ int c3_lf[19]  = {0,1,2,1,0,1,2,1,2,3,2,1,2,3,0,1,2,3,4};
__device__ __constant__ int c3_off[19] = {0,1,10,35,44,53,80,125,170,245,350,375,420,495,600,625,700,825,1000};

__device__ float g_C3[1225];

// ---------------------------------------------------------------------------
// Init kernel: real-basis Wigner 3j coupling tensors (double) + output zeroing
// ---------------------------------------------------------------------------
__device__ double dfac(int n) {
    double r = 1.0;
    for (int i = 2; i <= n; i++) r *= (double)i;
    return r;
}

__device__ double w3j_entry(int j1, int j2, int j3, int m1, int m2, int m3) {
    if (m1 + m2 + m3 != 0) return 0.0;
    int t1 = j2 - m1 - j3, t2 = j1 + m2 - j3;
    int kmin = 0; if (t1 > kmin) kmin = t1; if (t2 > kmin) kmin = t2;
    int kmax = j1 + j2 - j3;
    if (j1 - m1 < kmax) kmax = j1 - m1;
    if (j2 + m2 < kmax) kmax = j2 + m2;
    double s = 0.0;
    for (int k = kmin; k <= kmax; k++) {
        double d = dfac(k) * dfac(k - t1) * dfac(k - t2) * dfac(j1 + j2 - j3 - k)
                 * dfac(j1 - m1 - k) * dfac(j2 + m2 - k);
        s += ((k & 1) ? -1.0 : 1.0) / d;
    }
    int pw = j1 - j2 - m3;
    double sign = (pw & 1) ? -1.0 : 1.0;
    double pref = sign * sqrt(
        dfac(j1 + j2 - j3) * dfac(j1 - j2 + j3) * dfac(-j1 + j2 + j3) / dfac(j1 + j2 + j3 + 1)
        * dfac(j1 + m1) * dfac(j1 - m1) * dfac(j2 + m2) * dfac(j2 - m2)
        * dfac(j3 + m3) * dfac(j3 - m3));
    return pref * s;
}

__device__ void buildU(int l, double Ur[9][9], double Ui[9][9]) {
    for (int a = 0; a < 9; a++)
        for (int b = 0; b < 9; b++) { Ur[a][b] = 0.0; Ui[a][b] = 0.0; }
    Ur[l][l] = 1.0;
    const double s = 0.70710678118654752440;
    for (int m = 1; m <= l; m++) {
        Ur[l + m][l + m] = (m & 1) ? -s : s;
        Ur[l + m][l - m] = s;
        Ui[l - m][l - m] = s;
        Ui[l - m][l + m] = (m & 1) ? s : -s;
    }
}

__global__ void init_kernel(float* __restrict__ out, int n) {
    if (blockIdx.x >= 19) {
        // zero the output buffer: 512 floats per block
        int base = (blockIdx.x - 19) * 512 + threadIdx.x * 4;
        if (base + 3 < n) {
            *(float4*)&out[base] = make_float4(0.f, 0.f, 0.f, 0.f);
        } else {
            for (int i = base; i < min(base + 4, n); i++) out[i] = 0.0f;
        }
        return;
    }

    const int ci = blockIdx.x;
    const int lo = c3_lo[ci], li = c3_li[ci], lf = c3_lf[ci];
    const int n1 = 2 * lo + 1, n2 = 2 * li + 1, n3 = 2 * lf + 1;
    const int tid = threadIdx.x;

    __shared__ double wtab[25];
    __shared__ double Tre[225], Tim[225];
    __shared__ int    sUseReal;
    __shared__ double sInv;

    if (tid < n1 * n2) {
        int m1 = tid / n2 - lo;
        int m2 = tid % n2 - li;
        int m3 = -m1 - m2;
        double w = 0.0;
        if (m3 >= -lf && m3 <= lf) w = w3j_entry(lo, li, lf, m1, m2, m3);
        wtab[tid] = w;
    }
    __syncthreads();

    double U1r[9][9], U1i[9][9], U2r[9][9], U2i[9][9], U3r[9][9], U3i[9][9];
    buildU(lo, U1r, U1i);
    buildU(li, U2r, U2i);
    buildU(lf, U3r, U3i);

    const int ntot = n1 * n2 * n3;
    for (int o = tid; o < ntot; o += blockDim.x) {
        int a = o / (n2 * n3);
        int b = (o / n3) % n2;
        int c = o % n3;
        double sre = 0.0, sim = 0.0;
        for (int m = 0; m < n1; m++) {
            for (int nn2 = 0; nn2 < n2; nn2++) {
                double w = wtab[m * n2 + nn2];
                if (w == 0.0) continue;
                int m3 = -(m - lo) - (nn2 - li);
                int p = m3 + lf;
                double ar = U1r[a][m], ai = U1i[a][m];
                double br = U2r[b][nn2], bi = U2i[b][nn2];
                double pr = ar * br - ai * bi;
                double pi = ar * bi + ai * br;
                double cr = U3r[c][p], ci3 = U3i[c][p];
                sre += w * (pr * cr - pi * ci3);
                sim += w * (pr * ci3 + pi * cr);
            }
        }
        Tre[o] = sre;
        Tim[o] = sim;
    }
    __syncthreads();

    if (tid == 0) {
        double nr = 0.0, ni = 0.0;
        for (int t = 0; t < ntot; t++) { nr += Tre[t] * Tre[t]; ni += Tim[t] * Tim[t]; }
        int ur = (nr >= ni) ? 1 : 0;
        double nn = sqrt(ur ? nr : ni);
        sUseReal = ur;
        sInv = (nn > 0.0) ? (1.0 / nn) : 1.0;
    }
    __syncthreads();

    const int base = c3_off[ci];
    for (int o = tid; o < ntot; o += blockDim.x) {
        double v = (sUseReal ? Tre[o] : Tim[o]) * sInv;
        g_C3[base + o] = (float)v;
    }
}

// ---------------------------------------------------------------------------
// Fused edge kernel
// ---------------------------------------------------------------------------
__device__ __forceinline__ float swishf(float x) {
    return 1.679177f * x / (1.0f + expf(-x));
}

struct Smem {
    float F[TE * FEAT];       // gathered source features
    float Rsh[TE * RSHD];     // spherical harmonics
    float Acc[TE * FEAT];     // message accumulator
    float HT[HID * TE];       // hidden activations, k-major [k][edge]
    float BT[NBASIS * TE];    // gaussian basis, k-major
    float R[TE * SR_STR];     // current R block (padded stride)
    float C3[1225];
    int   Src[TE];
    int   Dst[TE];
    float Rad[TE];
};

// c3 offsets table (same as c3_off) readable in edge kernel
__device__ __constant__ int c3offL[19] = {0,1,10,35,44,53,80,125,170,245,350,375,420,495,600,625,700,825,1000};

template<int LO, int LI>
__device__ __forceinline__ void process_block(
    Smem* sm, const float* __restrict__ W3,
    int cb, int pcb, float normv, int tid)
{
    constexpr int NO = 2 * LO + 1;
    constexpr int NI = 2 * LI + 1;
    constexpr int LMIN = (LO < LI ? LO : LI);
    constexpr int LFMIN = (LO > LI ? LO - LI : LI - LO);
    constexpr int NLF = 2 * LMIN + 1;
    constexpr int FOI = (LI == 0 ? 0 : (LI == 1 ? 8 : 32));
    constexpr int FOO = (LO == 0 ? 0 : (LO == 1 ? 8 : 32));

    // ---- GEMM: sR[e][c] = h2[e] @ W3[:, cb+c] * 0.1,  c < 64*NLF ----
    {
        const int ct = tid & 63;       // column lane
        const int eg = tid >> 6;       // edge group: edges eg*8 .. eg*8+7
        float acc[NLF][8];
        #pragma unroll
        for (int cc = 0; cc < NLF; cc++)
            #pragma unroll
            for (int ee = 0; ee < 8; ee++) acc[cc][ee] = 0.0f;

        #pragma unroll 2
        for (int k = 0; k < HID; k++) {
            float4 ha = *(const float4*)&sm->HT[k * TE + eg * 8];
            float4 hb = *(const float4*)&sm->HT[k * TE + eg * 8 + 4];
            const float* wrow = W3 + k * RTOT + cb + ct;
            #pragma unroll
            for (int cc = 0; cc < NLF; cc++) {
                float w = wrow[64 * cc];
                acc[cc][0] += w * ha.x;
                acc[cc][1] += w * ha.y;
                acc[cc][2] += w * ha.z;
                acc[cc][3] += w * ha.w;
                acc[cc][4] += w * hb.x;
                acc[cc][5] += w * hb.y;
                acc[cc][6] += w * hb.z;
                acc[cc][7] += w * hb.w;
            }
        }
        #pragma unroll
        for (int cc = 0; cc < NLF; cc++)
            #pragma unroll
            for (int ee = 0; ee < 8; ee++)
                sm->R[(eg * 8 + ee) * SR_STR + ct + 64 * cc] = acc[cc][ee] * 0.1f;
    }
    __syncthreads();

    // ---- message: one thread per (e, o); loops all u in registers ----
    if (tid < TE * NO) {
        const int e = tid / NO;
        const int o = tid % NO;
        float aa[8];
        #pragma unroll
        for (int u = 0; u < 8; u++) aa[u] = 0.0f;

        #pragma unroll
        for (int fi = 0; fi < NLF; fi++) {
            const int lf = LFMIN + fi;
            const int nf = 2 * lf + 1;
            const float* C   = &sm->C3[c3offL[pcb + fi]];
            const float* ysh = &sm->Rsh[e * RSHD + lf * lf];

            float K[NI];
            #pragma unroll
            for (int i = 0; i < NI; i++) {
                float kk = 0.0f;
                #pragma unroll
                for (int mf = 0; mf < nf; mf++)
                    kk += C[(o * NI + i) * nf + mf] * ysh[mf];
                K[i] = kk;
            }

            const float* Fb = &sm->F[e * FEAT + FOI];
            float T[8];
            #pragma unroll
            for (int v = 0; v < 8; v++) {
                float tv = 0.0f;
                #pragma unroll
                for (int i = 0; i < NI; i++) tv += K[i] * Fb[v * NI + i];
                T[v] = tv;
            }

            const float* Rr = &sm->R[e * SR_STR];
            #pragma unroll
            for (int u = 0; u < 8; u++) {
                #pragma unroll
                for (int v = 0; v < 8; v++)
                    aa[u] += Rr[(u * 8 + v) * NLF + fi] * T[v];
            }
        }
        #pragma unroll
        for (int u = 0; u < 8; u++)
            sm->Acc[e * FEAT + FOO + u * NO + o] += normv * aa[u];
    }
    __syncthreads();
}

__global__ __launch_bounds__(NTHR, 2) void edge_kernel(
    const float* __restrict__ features,
    const int*   __restrict__ eidx,     // [2, E]
    const float* __restrict__ radii,
    const float* __restrict__ rsh,      // [E, 25]
    const float* __restrict__ W0,       // [10, 100]
    const float* __restrict__ W1,       // [100, 100]
    const float* __restrict__ W2,       // [100, 100]
    const float* __restrict__ W3,       // [100, 1216]
    float* __restrict__ out,            // [N, 72]
    int E)
{
    extern __shared__ char smem_raw[];
    Smem* sm = (Smem*)smem_raw;

    const int tid = threadIdx.x;
    const int e0  = blockIdx.x * TE;
    const int nE  = min(TE, E - e0);
    if (nE <= 0) return;

    for (int i = tid; i < 1225; i += NTHR) sm->C3[i] = g_C3[i];
    if (tid < TE) {
        int e = e0 + min(tid, nE - 1);
        sm->Src[tid] = eidx[e];
        sm->Dst[tid] = eidx[E + e];
        sm->Rad[tid] = radii[e];
    }
    __syncthreads();

    for (int f = tid; f < TE * FEAT; f += NTHR) {
        int e = f / FEAT, c = f % FEAT;
        sm->F[f] = features[sm->Src[e] * FEAT + c];
        sm->Acc[f] = 0.0f;
    }
    for (int f = tid; f < TE * RSHD; f += NTHR) {
        int e = f / RSHD, c = f % RSHD;
        int ge = e0 + min(e, nE - 1);
        sm->Rsh[f] = rsh[ge * RSHD + c];
    }
    for (int f = tid; f < TE * NBASIS; f += NTHR) {
        int b = f / TE, e = f % TE;
        float ctr = 0.7f + (float)b * (2.5f / 9.0f);
        float d = (sm->Rad[e] - ctr) * (9.0f / 2.5f);
        sm->BT[b * TE + e] = expf(-d * d);
    }
    __syncthreads();

    // ---------------- radial MLP: 3 swish layers ----------------
    {
        const int u  = tid & 127;
        const int eh = tid >> 7;        // 0/1 -> edges eh*16 .. eh*16+15
        float a[16];

        // layer 0: 10 -> 100, scale 1/sqrt(10)
        if (u < HID) {
            #pragma unroll
            for (int ee = 0; ee < 16; ee++) a[ee] = 0.0f;
            #pragma unroll
            for (int k = 0; k < NBASIS; k++) {
                float w = W0[k * HID + u];
                const float* bb = &sm->BT[k * TE + eh * 16];
                #pragma unroll
                for (int ee = 0; ee < 16; ee++) a[ee] += bb[ee] * w;
            }
            #pragma unroll
            for (int ee = 0; ee < 16; ee++)
                sm->HT[u * TE + eh * 16 + ee] = swishf(a[ee] * 0.31622776601683794f);
        }
        __syncthreads();

        // layers 1, 2: 100 -> 100, scale 0.1
        const float* Wl[2] = { W1, W2 };
        #pragma unroll
        for (int layer = 0; layer < 2; layer++) {
            if (u < HID) {
                #pragma unroll
                for (int ee = 0; ee < 16; ee++) a[ee] = 0.0f;
                #pragma unroll 2
                for (int k = 0; k < HID; k++) {
                    float w = Wl[layer][k * HID + u];
                    float4 h0 = *(const float4*)&sm->HT[k * TE + eh * 16];
                    float4 h1 = *(const float4*)&sm->HT[k * TE + eh * 16 + 4];
                    float4 h2 = *(const float4*)&sm->HT[k * TE + eh * 16 + 8];
                    float4 h3 = *(const float4*)&sm->HT[k * TE + eh * 16 + 12];
                    a[0]  += h0.x * w; a[1]  += h0.y * w; a[2]  += h0.z * w; a[3]  += h0.w * w;
                    a[4]  += h1.x * w; a[5]  += h1.y * w; a[6]  += h1.z * w; a[7]  += h1.w * w;
                    a[8]  += h2.x * w; a[9]  += h2.y * w; a[10] += h2.z * w; a[11] += h2.w * w;
                    a[12] += h3.x * w; a[13] += h3.y * w; a[14] += h3.z * w; a[15] += h3.w * w;
                }
            }
            __syncthreads();
            if (u < HID) {
                #pragma unroll
                for (int ee = 0; ee < 16; ee++)
                    sm->HT[u * TE + eh * 16 + ee] = swishf(a[ee] * 0.1f);
            }
            __syncthreads();
        }
    }

    // ---------------- 9 (lo,li) blocks ----------------
    const float n0 = sqrtf(12.566370614359172f * 1.0f / 24.0f);
    const float n1 = sqrtf(12.566370614359172f * 3.0f / 56.0f);
    const float n2 = sqrtf(12.566370614359172f * 5.0f / 72.0f);

    process_block<0, 0>(sm, W3,   0,  0, n0, tid);
    process_block<0, 1>(sm, W3,  64,  1, n0, tid);
    process_block<0, 2>(sm, W3, 128,  2, n0, tid);
    process_block<1, 0>(sm, W3, 192,  3, n1, tid);
    process_block<1, 1>(sm, W3, 256,  4, n1, tid);
    process_block<1, 2>(sm, W3, 448,  7, n1, tid);
    process_block<2, 0>(sm, W3, 640, 10, n2, tid);
    process_block<2, 1>(sm, W3, 704, 11, n2, tid);
    process_block<2, 2>(sm, W3, 896, 14, n2, tid);

    // ---------------- scatter-add ----------------
    for (int f = tid; f < nE * FEAT; f += NTHR) {
        int e = f / FEAT, c = f % FEAT;
        atomicAdd(&out[sm->Dst[e] * FEAT + c], sm->Acc[e * FEAT + c]);
    }
}

// ---------------------------------------------------------------------------
// Launch
// ---------------------------------------------------------------------------
extern "C" void kernel_launch(void* const* d_in, const int* in_sizes, int n_in,
                              void* d_out, int out_size) {
    const float* features = (const float*)d_in[0];
    const int*   eidx     = (const int*)  d_in[1];
    const float* radii    = (const float*)d_in[2];
    const float* rsh      = (const float*)d_in[3];
    const float* W0       = (const float*)d_in[4];
    const float* W1       = (const float*)d_in[5];
    const float* W2       = (const float*)d_in[6];
    const float* W3       = (const float*)d_in[7];
    float* out = (float*)d_out;

    const int E = in_sizes[2];

    static bool attr_set = false;
    if (!attr_set) {
        cudaFuncSetAttribute(edge_kernel,
                             cudaFuncAttributeMaxDynamicSharedMemorySize,
                             (int)sizeof(Smem));
        attr_set = true;
    }

    const int zblocks = (out_size + 511) / 512;
    init_kernel<<<19 + zblocks, 128>>>(out, out_size);

    const int nb = (E + TE - 1) / TE;
    edge_kernel<<<nb, NTHR, sizeof(Smem)>>>(features, eidx, radii, rsh,
                                            W0, W1, W2, W3, out, E);
}

// round 14
// speedup vs baseline: 1.4926x; 1.0018x over previous
#include <cuda_runtime.h>
#include <math.h>

// ---------------------------------------------------------------------------
// Problem constants
// ---------------------------------------------------------------------------
#define FEAT   72
#define RSHD   25
#define RTOT   1216
#define NBASIS 10
#define HID    100
#define TE     32       // edges per block
#define NTHR   256
#define SR_STR 324      // padded row stride for sR (kills bank conflicts)

// 19 (lo,li,lf) combos, lo-major / li / lf ascending
__device__ __constant__ int c3_lo[19]  = {0,0,0,1,1,1,1,1,1,1,2,2,2,2,2,2,2,2,2};
__device__ __constant__ int c3_li[19]  = {0,1,2,0,1,1,1,2,2,2,0,1,1,1,2,2,2,2,2};
__device__ __constant__ int c3_lf[19]  = {0,1,2,1,0,1,2,1,2,3,2,1,2,3,0,1,2,3,4};
__device__ __constant__ int c3_off[19] = {0,1,10,35,44,53,80,125,170,245,350,375,420,495,600,625,700,825,1000};

__device__ float g_C3[1225];

// ---------------------------------------------------------------------------
// Init kernel: real-basis Wigner 3j coupling tensors (double) + output zeroing
// ---------------------------------------------------------------------------
__device__ double dfac(int n) {
    double r = 1.0;
    for (int i = 2; i <= n; i++) r *= (double)i;
    return r;
}

__device__ double w3j_entry(int j1, int j2, int j3, int m1, int m2, int m3) {
    if (m1 + m2 + m3 != 0) return 0.0;
    int t1 = j2 - m1 - j3, t2 = j1 + m2 - j3;
    int kmin = 0; if (t1 > kmin) kmin = t1; if (t2 > kmin) kmin = t2;
    int kmax = j1 + j2 - j3;
    if (j1 - m1 < kmax) kmax = j1 - m1;
    if (j2 + m2 < kmax) kmax = j2 + m2;
    double s = 0.0;
    for (int k = kmin; k <= kmax; k++) {
        double d = dfac(k) * dfac(k - t1) * dfac(k - t2) * dfac(j1 + j2 - j3 - k)
                 * dfac(j1 - m1 - k) * dfac(j2 + m2 - k);
        s += ((k & 1) ? -1.0 : 1.0) / d;
    }
    int pw = j1 - j2 - m3;
    double sign = (pw & 1) ? -1.0 : 1.0;
    double pref = sign * sqrt(
        dfac(j1 + j2 - j3) * dfac(j1 - j2 + j3) * dfac(-j1 + j2 + j3) / dfac(j1 + j2 + j3 + 1)
        * dfac(j1 + m1) * dfac(j1 - m1) * dfac(j2 + m2) * dfac(j2 - m2)
        * dfac(j3 + m3) * dfac(j3 - m3));
    return pref * s;
}

__device__ void buildU(int l, double Ur[9][9], double Ui[9][9]) {
    for (int a = 0; a < 9; a++)
        for (int b = 0; b < 9; b++) { Ur[a][b] = 0.0; Ui[a][b] = 0.0; }
    Ur[l][l] = 1.0;
    const double s = 0.70710678118654752440;
    for (int m = 1; m <= l; m++) {
        Ur[l + m][l + m] = (m & 1) ? -s : s;
        Ur[l + m][l - m] = s;
        Ui[l - m][l - m] = s;
        Ui[l - m][l + m] = (m & 1) ? s : -s;
    }
}

__global__ void init_kernel(float* __restrict__ out, int n) {
    if (blockIdx.x >= 19) {
        // zero the output buffer: 512 floats per block
        int base = (blockIdx.x - 19) * 512 + threadIdx.x * 4;
        if (base + 3 < n) {
            *(float4*)&out[base] = make_float4(0.f, 0.f, 0.f, 0.f);
        } else {
            for (int i = base; i < min(base + 4, n); i++) out[i] = 0.0f;
        }
        return;
    }

    const int ci = blockIdx.x;
    const int lo = c3_lo[ci], li = c3_li[ci], lf = c3_lf[ci];
    const int n1 = 2 * lo + 1, n2 = 2 * li + 1, n3 = 2 * lf + 1;
    const int tid = threadIdx.x;

    __shared__ double wtab[25];
    __shared__ double Tre[225], Tim[225];
    __shared__ int    sUseReal;
    __shared__ double sInv;

    if (tid < n1 * n2) {
        int m1 = tid / n2 - lo;
        int m2 = tid % n2 - li;
        int m3 = -m1 - m2;
        double w = 0.0;
        if (m3 >= -lf && m3 <= lf) w = w3j_entry(lo, li, lf, m1, m2, m3);
        wtab[tid] = w;
    }
    __syncthreads();

    double U1r[9][9], U1i[9][9], U2r[9][9], U2i[9][9], U3r[9][9], U3i[9][9];
    buildU(lo, U1r, U1i);
    buildU(li, U2r, U2i);
    buildU(lf, U3r, U3i);

    const int ntot = n1 * n2 * n3;
    for (int o = tid; o < ntot; o += blockDim.x) {
        int a = o / (n2 * n3);
        int b = (o / n3) % n2;
        int c = o % n3;
        double sre = 0.0, sim = 0.0;
        for (int m = 0; m < n1; m++) {
            for (int nn2 = 0; nn2 < n2; nn2++) {
                double w = wtab[m * n2 + nn2];
                if (w == 0.0) continue;
                int m3 = -(m - lo) - (nn2 - li);
                int p = m3 + lf;
                double ar = U1r[a][m], ai = U1i[a][m];
                double br = U2r[b][nn2], bi = U2i[b][nn2];
                double pr = ar * br - ai * bi;
                double pi = ar * bi + ai * br;
                double cr = U3r[c][p], ci3 = U3i[c][p];
                sre += w * (pr * cr - pi * ci3);
                sim += w * (pr * ci3 + pi * cr);
            }
        }
        Tre[o] = sre;
        Tim[o] = sim;
    }
    __syncthreads();

    if (tid == 0) {
        double nr = 0.0, ni = 0.0;
        for (int t = 0; t < ntot; t++) { nr += Tre[t] * Tre[t]; ni += Tim[t] * Tim[t]; }
        int ur = (nr >= ni) ? 1 : 0;
        double nn = sqrt(ur ? nr : ni);
        sUseReal = ur;
        sInv = (nn > 0.0) ? (1.0 / nn) : 1.0;
    }
    __syncthreads();

    const int base = c3_off[ci];
    for (int o = tid; o < ntot; o += blockDim.x) {
        double v = (sUseReal ? Tre[o] : Tim[o]) * sInv;
        g_C3[base + o] = (float)v;
    }
}

// ---------------------------------------------------------------------------
// Fused edge kernel
// ---------------------------------------------------------------------------
__device__ __forceinline__ float swishf(float x) {
    return 1.679177f * x / (1.0f + expf(-x));
}

struct Smem {
    float F[TE * FEAT];       // gathered source features
    float Rsh[TE * RSHD];     // spherical harmonics
    float Acc[TE * FEAT];     // message accumulator
    float HT[HID * TE];       // hidden activations, k-major [k][edge]
    float BT[NBASIS * TE];    // gaussian basis, k-major
    float R[TE * SR_STR];     // current R block (padded stride)
    float C3[1225];
    int   Src[TE];
    int   Dst[TE];
    float Rad[TE];
};

// c3 offsets table (same as c3_off) readable in edge kernel
__device__ __constant__ int c3offL[19] = {0,1,10,35,44,53,80,125,170,245,350,375,420,495,600,625,700,825,1000};

template<int LO, int LI>
__device__ __forceinline__ void process_block(
    Smem* sm, const float* __restrict__ W3,
    int cb, int pcb, float normv, int tid)
{
    constexpr int NO = 2 * LO + 1;
    constexpr int NI = 2 * LI + 1;
    constexpr int LMIN = (LO < LI ? LO : LI);
    constexpr int LFMIN = (LO > LI ? LO - LI : LI - LO);
    constexpr int NLF = 2 * LMIN + 1;
    constexpr int FOI = (LI == 0 ? 0 : (LI == 1 ? 8 : 32));
    constexpr int FOO = (LO == 0 ? 0 : (LO == 1 ? 8 : 32));

    // ---- GEMM: sR[e][c] = h2[e] @ W3[:, cb+c] * 0.1,  c < 64*NLF ----
    {
        const int ct = tid & 63;       // column lane
        const int eg = tid >> 6;       // edge group: edges eg*8 .. eg*8+7
        float acc[NLF][8];
        #pragma unroll
        for (int cc = 0; cc < NLF; cc++)
            #pragma unroll
            for (int ee = 0; ee < 8; ee++) acc[cc][ee] = 0.0f;

        #pragma unroll 2
        for (int k = 0; k < HID; k++) {
            float4 ha = *(const float4*)&sm->HT[k * TE + eg * 8];
            float4 hb = *(const float4*)&sm->HT[k * TE + eg * 8 + 4];
            const float* wrow = W3 + k * RTOT + cb + ct;
            #pragma unroll
            for (int cc = 0; cc < NLF; cc++) {
                float w = wrow[64 * cc];
                acc[cc][0] += w * ha.x;
                acc[cc][1] += w * ha.y;
                acc[cc][2] += w * ha.z;
                acc[cc][3] += w * ha.w;
                acc[cc][4] += w * hb.x;
                acc[cc][5] += w * hb.y;
                acc[cc][6] += w * hb.z;
                acc[cc][7] += w * hb.w;
            }
        }
        #pragma unroll
        for (int cc = 0; cc < NLF; cc++)
            #pragma unroll
            for (int ee = 0; ee < 8; ee++)
                sm->R[(eg * 8 + ee) * SR_STR + ct + 64 * cc] = acc[cc][ee] * 0.1f;
    }
    __syncthreads();

    // ---- message: one thread per (e, o); loops all u in registers ----
    if (tid < TE * NO) {
        const int e = tid / NO;
        const int o = tid % NO;
        float aa[8];
        #pragma unroll
        for (int u = 0; u < 8; u++) aa[u] = 0.0f;

        #pragma unroll
        for (int fi = 0; fi < NLF; fi++) {
            const int lf = LFMIN + fi;
            const int nf = 2 * lf + 1;
            const float* C   = &sm->C3[c3offL[pcb + fi]];
            const float* ysh = &sm->Rsh[e * RSHD + lf * lf];

            float K[NI];
            #pragma unroll
            for (int i = 0; i < NI; i++) {
                float kk = 0.0f;
                #pragma unroll
                for (int mf = 0; mf < nf; mf++)
                    kk += C[(o * NI + i) * nf + mf] * ysh[mf];
                K[i] = kk;
            }

            const float* Fb = &sm->F[e * FEAT + FOI];
            float T[8];
            #pragma unroll
            for (int v = 0; v < 8; v++) {
                float tv = 0.0f;
                #pragma unroll
                for (int i = 0; i < NI; i++) tv += K[i] * Fb[v * NI + i];
                T[v] = tv;
            }

            const float* Rr = &sm->R[e * SR_STR];
            #pragma unroll
            for (int u = 0; u < 8; u++) {
                #pragma unroll
                for (int v = 0; v < 8; v++)
                    aa[u] += Rr[(u * 8 + v) * NLF + fi] * T[v];
            }
        }
        #pragma unroll
        for (int u = 0; u < 8; u++)
            sm->Acc[e * FEAT + FOO + u * NO + o] += normv * aa[u];
    }
    __syncthreads();
}

__global__ __launch_bounds__(NTHR, 2) void edge_kernel(
    const float* __restrict__ features,
    const int*   __restrict__ eidx,     // [2, E]
    const float* __restrict__ radii,
    const float* __restrict__ rsh,      // [E, 25]
    const float* __restrict__ W0,       // [10, 100]
    const float* __restrict__ W1,       // [100, 100]
    const float* __restrict__ W2,       // [100, 100]
    const float* __restrict__ W3,       // [100, 1216]
    float* __restrict__ out,            // [N, 72]
    int E)
{
    extern __shared__ char smem_raw[];
    Smem* sm = (Smem*)smem_raw;

    const int tid = threadIdx.x;
    const int e0  = blockIdx.x * TE;
    const int nE  = min(TE, E - e0);
    if (nE <= 0) return;

    for (int i = tid; i < 1225; i += NTHR) sm->C3[i] = g_C3[i];
    if (tid < TE) {
        int e = e0 + min(tid, nE - 1);
        sm->Src[tid] = eidx[e];
        sm->Dst[tid] = eidx[E + e];
        sm->Rad[tid] = radii[e];
    }
    __syncthreads();

    for (int f = tid; f < TE * FEAT; f += NTHR) {
        int e = f / FEAT, c = f % FEAT;
        sm->F[f] = features[sm->Src[e] * FEAT + c];
        sm->Acc[f] = 0.0f;
    }
    for (int f = tid; f < TE * RSHD; f += NTHR) {
        int e = f / RSHD, c = f % RSHD;
        int ge = e0 + min(e, nE - 1);
        sm->Rsh[f] = rsh[ge * RSHD + c];
    }
    for (int f = tid; f < TE * NBASIS; f += NTHR) {
        int b = f / TE, e = f % TE;
        float ctr = 0.7f + (float)b * (2.5f / 9.0f);
        float d = (sm->Rad[e] - ctr) * (9.0f / 2.5f);
        sm->BT[b * TE + e] = expf(-d * d);
    }
    __syncthreads();

    // ---------------- radial MLP: 3 swish layers ----------------
    {
        const int u  = tid & 127;
        const int eh = tid >> 7;        // 0/1 -> edges eh*16 .. eh*16+15
        float a[16];

        // layer 0: 10 -> 100, scale 1/sqrt(10)
        if (u < HID) {
            #pragma unroll
            for (int ee = 0; ee < 16; ee++) a[ee] = 0.0f;
            #pragma unroll
            for (int k = 0; k < NBASIS; k++) {
                float w = W0[k * HID + u];
                const float* bb = &sm->BT[k * TE + eh * 16];
                #pragma unroll
                for (int ee = 0; ee < 16; ee++) a[ee] += bb[ee] * w;
            }
            #pragma unroll
            for (int ee = 0; ee < 16; ee++)
                sm->HT[u * TE + eh * 16 + ee] = swishf(a[ee] * 0.31622776601683794f);
        }
        __syncthreads();

        // layers 1, 2: 100 -> 100, scale 0.1
        const float* Wl[2] = { W1, W2 };
        #pragma unroll
        for (int layer = 0; layer < 2; layer++) {
            if (u < HID) {
                #pragma unroll
                for (int ee = 0; ee < 16; ee++) a[ee] = 0.0f;
                #pragma unroll 2
                for (int k = 0; k < HID; k++) {
                    float w = Wl[layer][k * HID + u];
                    float4 h0 = *(const float4*)&sm->HT[k * TE + eh * 16];
                    float4 h1 = *(const float4*)&sm->HT[k * TE + eh * 16 + 4];
                    float4 h2 = *(const float4*)&sm->HT[k * TE + eh * 16 + 8];
                    float4 h3 = *(const float4*)&sm->HT[k * TE + eh * 16 + 12];
                    a[0]  += h0.x * w; a[1]  += h0.y * w; a[2]  += h0.z * w; a[3]  += h0.w * w;
                    a[4]  += h1.x * w; a[5]  += h1.y * w; a[6]  += h1.z * w; a[7]  += h1.w * w;
                    a[8]  += h2.x * w; a[9]  += h2.y * w; a[10] += h2.z * w; a[11] += h2.w * w;
                    a[12] += h3.x * w; a[13] += h3.y * w; a[14] += h3.z * w; a[15] += h3.w * w;
                }
            }
            __syncthreads();
            if (u < HID) {
                #pragma unroll
                for (int ee = 0; ee < 16; ee++)
                    sm->HT[u * TE + eh * 16 + ee] = swishf(a[ee] * 0.1f);
            }
            __syncthreads();
        }
    }

    // ---------------- 9 (lo,li) blocks ----------------
    const float n0 = sqrtf(12.566370614359172f * 1.0f / 24.0f);
    const float n1 = sqrtf(12.566370614359172f * 3.0f / 56.0f);
    const float n2 = sqrtf(12.566370614359172f * 5.0f / 72.0f);

    process_block<0, 0>(sm, W3,   0,  0, n0, tid);
    process_block<0, 1>(sm, W3,  64,  1, n0, tid);
    process_block<0, 2>(sm, W3, 128,  2, n0, tid);
    process_block<1, 0>(sm, W3, 192,  3, n1, tid);
    process_block<1, 1>(sm, W3, 256,  4, n1, tid);
    process_block<1, 2>(sm, W3, 448,  7, n1, tid);
    process_block<2, 0>(sm, W3, 640, 10, n2, tid);
    process_block<2, 1>(sm, W3, 704, 11, n2, tid);
    process_block<2, 2>(sm, W3, 896, 14, n2, tid);

    // ---------------- scatter-add ----------------
    for (int f = tid; f < nE * FEAT; f += NTHR) {
        int e = f / FEAT, c = f % FEAT;
        atomicAdd(&out[sm->Dst[e] * FEAT + c], sm->Acc[e * FEAT + c]);
    }
}

// ---------------------------------------------------------------------------
// Launch
// ---------------------------------------------------------------------------
extern "C" void kernel_launch(void* const* d_in, const int* in_sizes, int n_in,
                              void* d_out, int out_size) {
    const float* features = (const float*)d_in[0];
    const int*   eidx     = (const int*)  d_in[1];
    const float* radii    = (const float*)d_in[2];
    const float* rsh      = (const float*)d_in[3];
    const float* W0       = (const float*)d_in[4];
    const float* W1       = (const float*)d_in[5];
    const float* W2       = (const float*)d_in[6];
    const float* W3       = (const float*)d_in[7];
    float* out = (float*)d_out;

    const int E = in_sizes[2];

    static bool attr_set = false;
    if (!attr_set) {
        cudaFuncSetAttribute(edge_kernel,
                             cudaFuncAttributeMaxDynamicSharedMemorySize,
                             (int)sizeof(Smem));
        attr_set = true;
    }

    const int zblocks = (out_size + 511) / 512;
    init_kernel<<<19 + zblocks, 128>>>(out, out_size);

    const int nb = (E + TE - 1) / TE;
    edge_kernel<<<nb, NTHR, sizeof(Smem)>>>(features, eidx, radii, rsh,
                                            W0, W1, W2, W3, out, E);
}

// round 15
// speedup vs baseline: 1.8488x; 1.2386x over previous
#include <cuda_runtime.h>
#include <math.h>

#define FEAT   72
#define RSHD   25
#define RTOT   1216
#define NBASIS 10
#define HID    100
#define TE     16
#define NTHR   256
#define SR_STR 325

__device__ __constant__ int c3_lo[19]  = {0,0,0,1,1,1,1,1,1,1,2,2,2,2,2,2,2,2,2};
__device__ __constant__ int c3_li[19]  = {0,1,2,0,1,1,1,2,2,2,0,1,1,1,2,2,2,2,2};
__device__ __constant__ int c3_lf[19]  = {0,1,2,1,0,1,2,1,2,3,2,1,2,3,0,1,2,3,4};
__device__ __constant__ int c3_off[19] = {0,1,10,35,44,53,80,125,170,245,350,375,420,495,600,625,700,825,1000};
__device__ __constant__ int c3offL[19] = {0,1,10,35,44,53,80,125,170,245,350,375,420,495,600,625,700,825,1000};

__device__ float g_C3[1225];

// ---------------------------------------------------------------------------
// Init: Wigner 3j real coupling tensors (double precision) + output zeroing
// ---------------------------------------------------------------------------
__device__ double dfac(int n) {
    double r = 1.0;
    for (int i = 2; i <= n; i++) r *= (double)i;
    return r;
}

__device__ double w3j_entry(int j1, int j2, int j3, int m1, int m2, int m3) {
    if (m1 + m2 + m3 != 0) return 0.0;
    int t1 = j2 - m1 - j3, t2 = j1 + m2 - j3;
    int kmin = 0; if (t1 > kmin) kmin = t1; if (t2 > kmin) kmin = t2;
    int kmax = j1 + j2 - j3;
    if (j1 - m1 < kmax) kmax = j1 - m1;
    if (j2 + m2 < kmax) kmax = j2 + m2;
    double s = 0.0;
    for (int k = kmin; k <= kmax; k++) {
        double d = dfac(k) * dfac(k - t1) * dfac(k - t2) * dfac(j1 + j2 - j3 - k)
                 * dfac(j1 - m1 - k) * dfac(j2 + m2 - k);
        s += ((k & 1) ? -1.0 : 1.0) / d;
    }
    double sign = ((j1 - j2 - m3) & 1) ? -1.0 : 1.0;
    double pref = sign * sqrt(
        dfac(j1 + j2 - j3) * dfac(j1 - j2 + j3) * dfac(-j1 + j2 + j3) / dfac(j1 + j2 + j3 + 1)
        * dfac(j1 + m1) * dfac(j1 - m1) * dfac(j2 + m2) * dfac(j2 - m2)
        * dfac(j3 + m3) * dfac(j3 - m3));
    return pref * s;
}

__device__ void buildU(int l, double Ur[9][9], double Ui[9][9]) {
    for (int a = 0; a < 9; a++)
        for (int b = 0; b < 9; b++) { Ur[a][b] = 0.0; Ui[a][b] = 0.0; }
    Ur[l][l] = 1.0;
    const double s = 0.70710678118654752440;
    for (int m = 1; m <= l; m++) {
        Ur[l + m][l + m] = (m & 1) ? -s : s;
        Ur[l + m][l - m] = s;
        Ui[l - m][l - m] = s;
        Ui[l - m][l + m] = (m & 1) ? s : -s;
    }
}

__global__ void init_kernel(float* __restrict__ out, int n) {
    if (blockIdx.x >= 19) {
        int base = (blockIdx.x - 19) * 512 + threadIdx.x * 4;
        if (base + 3 < n) {
            *(float4*)&out[base] = make_float4(0.f, 0.f, 0.f, 0.f);
        } else {
            for (int i = base; i < min(base + 4, n); i++) out[i] = 0.0f;
        }
        return;
    }

    const int ci = blockIdx.x;
    const int lo = c3_lo[ci], li = c3_li[ci], lf = c3_lf[ci];
    const int n1 = 2 * lo + 1, n2 = 2 * li + 1, n3 = 2 * lf + 1;
    const int tid = threadIdx.x;

    __shared__ double wtab[25];
    __shared__ double Tre[225], Tim[225];
    __shared__ int    sUseReal;
    __shared__ double sInv;

    if (tid < n1 * n2) {
        int m1 = tid / n2 - lo;
        int m2 = tid % n2 - li;
        int m3 = -m1 - m2;
        double w = 0.0;
        if (m3 >= -lf && m3 <= lf) w = w3j_entry(lo, li, lf, m1, m2, m3);
        wtab[tid] = w;
    }
    __syncthreads();

    double U1r[9][9], U1i[9][9], U2r[9][9], U2i[9][9], U3r[9][9], U3i[9][9];
    buildU(lo, U1r, U1i);
    buildU(li, U2r, U2i);
    buildU(lf, U3r, U3i);

    const int ntot = n1 * n2 * n3;
    for (int o = tid; o < ntot; o += blockDim.x) {
        int a = o / (n2 * n3);
        int b = (o / n3) % n2;
        int c = o % n3;
        double sre = 0.0, sim = 0.0;
        for (int m = 0; m < n1; m++) {
            for (int nn = 0; nn < n2; nn++) {
                double w = wtab[m * n2 + nn];
                if (w == 0.0) continue;
                int m3 = -(m - lo) - (nn - li);
                int p = m3 + lf;
                double ar = U1r[a][m], ai = U1i[a][m];
                double br = U2r[b][nn], bi = U2i[b][nn];
                double pr = ar * br - ai * bi;
                double pi = ar * bi + ai * br;
                double cr = U3r[c][p], ci3 = U3i[c][p];
                sre += w * (pr * cr - pi * ci3);
                sim += w * (pr * ci3 + pi * cr);
            }
        }
        Tre[o] = sre;
        Tim[o] = sim;
    }
    __syncthreads();

    if (tid == 0) {
        double nr = 0.0, ni = 0.0;
        for (int t = 0; t < ntot; t++) { nr += Tre[t] * Tre[t]; ni += Tim[t] * Tim[t]; }
        int ur = (nr >= ni) ? 1 : 0;
        double nn = sqrt(ur ? nr : ni);
        sUseReal = ur;
        sInv = (nn > 0.0) ? (1.0 / nn) : 1.0;
    }
    __syncthreads();

    const int base = c3_off[ci];
    for (int o = tid; o < ntot; o += blockDim.x) {
        double v = (sUseReal ? Tre[o] : Tim[o]) * sInv;
        g_C3[base + o] = (float)v;
    }
}

// ---------------------------------------------------------------------------
// Fused edge kernel
// ---------------------------------------------------------------------------
__device__ __forceinline__ float swishf(float x) {
    return 1.679177f * x / (1.0f + expf(-x));
}

struct Smem {
    float F[TE * FEAT];
    float Rsh[TE * RSHD];
    float Acc[TE * FEAT];
    float HT[HID * TE];        // k-major [k][edge]
    float BT[NBASIS * TE];
    float R[TE * SR_STR];
    float C3[1225];
    int   Src[TE];
    int   Dst[TE];
    float Rad[TE];
};

template<int LO, int LI>
__device__ __forceinline__ void process_block(
    Smem* sm, const float* __restrict__ W3,
    int cb, int pcb, float normv, int tid)
{
    constexpr int NO = 2 * LO + 1;
    constexpr int NI = 2 * LI + 1;
    constexpr int LMIN = (LO < LI ? LO : LI);
    constexpr int LFMIN = (LO > LI ? LO - LI : LI - LO);
    constexpr int NLF = 2 * LMIN + 1;
    constexpr int FOI = (LI == 0 ? 0 : (LI == 1 ? 8 : 32));
    constexpr int FOO = (LO == 0 ? 0 : (LO == 1 ? 8 : 32));
    constexpr int PF  = (NLF == 1) ? 4 : 2;   // k-prefetch depth

    // ---- GEMM: sR[e][c] = h2[e] @ W3[:, cb+c] * 0.1,  c < 64*NLF ----
    {
        const int ct = tid & 63;       // column lane
        const int eg = tid >> 6;       // edge group: edges eg*4 .. eg*4+3
        const float* wp = W3 + cb + ct;

        float acc[NLF][4];
        #pragma unroll
        for (int cc = 0; cc < NLF; cc++)
            #pragma unroll
            for (int ee = 0; ee < 4; ee++) acc[cc][ee] = 0.0f;

        float w[PF][NLF];
        #pragma unroll
        for (int pp = 0; pp < PF; pp++)
            #pragma unroll
            for (int cc = 0; cc < NLF; cc++)
                w[pp][cc] = wp[pp * RTOT + 64 * cc];

        for (int k0 = 0; k0 < HID; k0 += PF) {
            float wn[PF][NLF];
            if (k0 + PF < HID) {
                #pragma unroll
                for (int pp = 0; pp < PF; pp++)
                    #pragma unroll
                    for (int cc = 0; cc < NLF; cc++)
                        wn[pp][cc] = wp[(k0 + PF + pp) * RTOT + 64 * cc];
            }
            #pragma unroll
            for (int pp = 0; pp < PF; pp++) {
                float4 h = *(const float4*)&sm->HT[(k0 + pp) * TE + eg * 4];
                #pragma unroll
                for (int cc = 0; cc < NLF; cc++) {
                    acc[cc][0] += w[pp][cc] * h.x;
                    acc[cc][1] += w[pp][cc] * h.y;
                    acc[cc][2] += w[pp][cc] * h.z;
                    acc[cc][3] += w[pp][cc] * h.w;
                }
            }
            #pragma unroll
            for (int pp = 0; pp < PF; pp++)
                #pragma unroll
                for (int cc = 0; cc < NLF; cc++)
                    w[pp][cc] = wn[pp][cc];
        }
        #pragma unroll
        for (int cc = 0; cc < NLF; cc++)
            #pragma unroll
            for (int ee = 0; ee < 4; ee++)
                sm->R[(eg * 4 + ee) * SR_STR + ct + 64 * cc] = acc[cc][ee] * 0.1f;
    }
    __syncthreads();

    // ---- message: one thread per (e, o); all u in registers ----
    if (tid < TE * NO) {
        const int e = tid / NO;
        const int o = tid % NO;
        float aa[8];
        #pragma unroll
        for (int u = 0; u < 8; u++) aa[u] = 0.0f;

        #pragma unroll
        for (int fi = 0; fi < NLF; fi++) {
            const int lf = LFMIN + fi;
            const int nf = 2 * lf + 1;
            const float* C   = &sm->C3[c3offL[pcb + fi]];
            const float* ysh = &sm->Rsh[e * RSHD + lf * lf];

            float K[NI];
            #pragma unroll
            for (int i = 0; i < NI; i++) {
                float kk = 0.0f;
                #pragma unroll
                for (int mf = 0; mf < nf; mf++)
                    kk += C[(o * NI + i) * nf + mf] * ysh[mf];
                K[i] = kk;
            }

            const float* Fb = &sm->F[e * FEAT + FOI];
            float T[8];
            #pragma unroll
            for (int v = 0; v < 8; v++) {
                float tv = 0.0f;
                #pragma unroll
                for (int i = 0; i < NI; i++) tv += K[i] * Fb[v * NI + i];
                T[v] = tv;
            }

            const float* Rr = &sm->R[e * SR_STR];
            #pragma unroll
            for (int u = 0; u < 8; u++) {
                #pragma unroll
                for (int v = 0; v < 8; v++)
                    aa[u] += Rr[(u * 8 + v) * NLF + fi] * T[v];
            }
        }
        #pragma unroll
        for (int u = 0; u < 8; u++)
            sm->Acc[e * FEAT + FOO + u * NO + o] += normv * aa[u];
    }
    __syncthreads();
}

__global__ __launch_bounds__(NTHR, 4) void edge_kernel(
    const float* __restrict__ features,
    const int*   __restrict__ eidx,
    const float* __restrict__ radii,
    const float* __restrict__ rsh,
    const float* __restrict__ W0,
    const float* __restrict__ W1,
    const float* __restrict__ W2,
    const float* __restrict__ W3,
    float* __restrict__ out,
    int E)
{
    __shared__ Smem smem;
    Smem* sm = &smem;

    const int tid = threadIdx.x;
    const int e0  = blockIdx.x * TE;
    const int nE  = min(TE, E - e0);
    if (nE <= 0) return;

    for (int i = tid; i < 1225; i += NTHR) sm->C3[i] = g_C3[i];
    if (tid < TE) {
        int e = e0 + min(tid, nE - 1);
        sm->Src[tid] = eidx[e];
        sm->Dst[tid] = eidx[E + e];
        sm->Rad[tid] = radii[e];
    }
    __syncthreads();

    for (int f = tid; f < TE * FEAT; f += NTHR) {
        int e = f / FEAT, c = f % FEAT;
        sm->F[f] = features[sm->Src[e] * FEAT + c];
        sm->Acc[f] = 0.0f;
    }
    for (int f = tid; f < TE * RSHD; f += NTHR) {
        int e = f / RSHD, c = f % RSHD;
        int ge = e0 + min(e, nE - 1);
        sm->Rsh[f] = rsh[ge * RSHD + c];
    }
    if (tid < TE * NBASIS) {
        int b = tid / TE, e = tid % TE;
        float ctr = 0.7f + (float)b * (2.5f / 9.0f);
        float d = (sm->Rad[e] - ctr) * (9.0f / 2.5f);
        sm->BT[b * TE + e] = expf(-d * d);
    }
    __syncthreads();

    // ---------------- radial MLP: 3 swish layers ----------------
    {
        const int u  = tid & 127;
        const int eh = tid >> 7;        // 0/1 -> edges eh*8 .. eh*8+7
        float a[8];

        // layer 0: 10 -> 100, scale 1/sqrt(10)
        if (u < HID) {
            #pragma unroll
            for (int ee = 0; ee < 8; ee++) a[ee] = 0.0f;
            #pragma unroll
            for (int k = 0; k < NBASIS; k++) {
                float w = W0[k * HID + u];
                const float* bb = &sm->BT[k * TE + eh * 8];
                #pragma unroll
                for (int ee = 0; ee < 8; ee++) a[ee] += bb[ee] * w;
            }
            #pragma unroll
            for (int ee = 0; ee < 8; ee++)
                sm->HT[u * TE + eh * 8 + ee] = swishf(a[ee] * 0.31622776601683794f);
        }
        __syncthreads();

        // layers 1, 2: 100 -> 100, scale 0.1
        const float* Wl[2] = { W1, W2 };
        #pragma unroll
        for (int layer = 0; layer < 2; layer++) {
            if (u < HID) {
                #pragma unroll
                for (int ee = 0; ee < 8; ee++) a[ee] = 0.0f;
                float wcur = Wl[layer][u];
                #pragma unroll 4
                for (int k = 0; k < HID; k++) {
                    float wnext = (k + 1 < HID) ? Wl[layer][(k + 1) * HID + u] : 0.0f;
                    float4 h0 = *(const float4*)&sm->HT[k * TE + eh * 8];
                    float4 h1 = *(const float4*)&sm->HT[k * TE + eh * 8 + 4];
                    a[0] += h0.x * wcur; a[1] += h0.y * wcur;
                    a[2] += h0.z * wcur; a[3] += h0.w * wcur;
                    a[4] += h1.x * wcur; a[5] += h1.y * wcur;
                    a[6] += h1.z * wcur; a[7] += h1.w * wcur;
                    wcur = wnext;
                }
            }
            __syncthreads();
            if (u < HID) {
                #pragma unroll
                for (int ee = 0; ee < 8; ee++)
                    sm->HT[u * TE + eh * 8 + ee] = swishf(a[ee] * 0.1f);
            }
            __syncthreads();
        }
    }

    // ---------------- 9 (lo,li) blocks ----------------
    const float n0 = sqrtf(12.566370614359172f * 1.0f / 24.0f);
    const float n1 = sqrtf(12.566370614359172f * 3.0f / 56.0f);
    const float n2 = sqrtf(12.566370614359172f * 5.0f / 72.0f);

    process_block<0, 0>(sm, W3,   0,  0, n0, tid);
    process_block<0, 1>(sm, W3,  64,  1, n0, tid);
    process_block<0, 2>(sm, W3, 128,  2, n0, tid);
    process_block<1, 0>(sm, W3, 192,  3, n1, tid);
    process_block<1, 1>(sm, W3, 256,  4, n1, tid);
    process_block<1, 2>(sm, W3, 448,  7, n1, tid);
    process_block<2, 0>(sm, W3, 640, 10, n2, tid);
    process_block<2, 1>(sm, W3, 704, 11, n2, tid);
    process_block<2, 2>(sm, W3, 896, 14, n2, tid);

    // ---------------- scatter-add ----------------
    for (int f = tid; f < nE * FEAT; f += NTHR) {
        int e = f / FEAT, c = f % FEAT;
        atomicAdd(&out[sm->Dst[e] * FEAT + c], sm->Acc[e * FEAT + c]);
    }
}

// ---------------------------------------------------------------------------
// Launch
// ---------------------------------------------------------------------------
extern "C" void kernel_launch(void* const* d_in, const int* in_sizes, int n_in,
                              void* d_out, int out_size) {
    const float* features = (const float*)d_in[0];
    const int*   eidx     = (const int*)  d_in[1];
    const float* radii    = (const float*)d_in[2];
    const float* rsh      = (const float*)d_in[3];
    const float* W0       = (const float*)d_in[4];
    const float* W1       = (const float*)d_in[5];
    const float* W2       = (const float*)d_in[6];
    const float* W3       = (const float*)d_in[7];
    float* out = (float*)d_out;

    const int E = in_sizes[2];

    const int zblocks = (out_size + 511) / 512;
    init_kernel<<<19 + zblocks, 128>>>(out, out_size);

    const int nb = (E + TE - 1) / TE;
    edge_kernel<<<nb, NTHR>>>(features, eidx, radii, rsh, W0, W1, W2, W3, out, E);
}

// round 17
// speedup vs baseline: 2.5532x; 1.3810x over previous
#include <cuda_runtime.h>
#include <cuda_bf16.h>
#include <math.h>
#include <stdint.h>

#define FEAT   72
#define RSHD   25
#define RTOT   1216
#define NBASIS 10
#define HID    100
#define NTHR   256
#define MTE    16
#define ETILE  128
#define NETILE 6256     // 782 blocks * 8 row-tiles
#define RSTR   66

__device__ float    g_C3[1225];
__device__ uint32_t g_Ahi[(size_t)NETILE * 896];
__device__ uint32_t g_Alo[(size_t)NETILE * 896];
__device__ uint4    g_B[19 * 8 * 7 * 32];

__device__ __constant__ int c3_lo[19]  = {0,0,0,1,1,1,1,1,1,1,2,2,2,2,2,2,2,2,2};
__device__ __constant__ int c3_li[19]  = {0,1,2,0,1,1,1,2,2,2,0,1,1,1,2,2,2,2,2};
__device__ __constant__ int c3_lf[19]  = {0,1,2,1,0,1,2,1,2,3,2,1,2,3,0,1,2,3,4};
__device__ __constant__ int c3_off[19] = {0,1,10,35,44,53,80,125,170,245,350,375,420,495,600,625,700,825,1000};
__device__ __constant__ int c3offL[19] = {0,1,10,35,44,53,80,125,170,245,350,375,420,495,600,625,700,825,1000};
// 19 fi-subs in block order (lo-major, li, fi ascending)
__device__ __constant__ int sub_cb[19]  = {0,64,128,192,256,256,256,448,448,448,640,704,704,704,896,896,896,896,896};
__device__ __constant__ int sub_nlf[19] = {1,1,1,1,3,3,3,3,3,3,1,3,3,3,5,5,5,5,5};
__device__ __constant__ int sub_fi[19]  = {0,0,0,0,0,1,2,0,1,2,0,0,1,2,0,1,2,3,4};

// ---------------------------------------------------------------------------
// mma.sync wrapper (baseline sm_80+ PTX, works on target sm_103)
// ---------------------------------------------------------------------------
__device__ __forceinline__ void mma_bf16(float d[4], uint4 a, uint32_t b0, uint32_t b1) {
    asm volatile("mma.sync.aligned.m16n8k16.row.col.f32.bf16.bf16.f32 "
        "{%0,%1,%2,%3}, {%4,%5,%6,%7}, {%8,%9}, {%0,%1,%2,%3};"
        : "+f"(d[0]), "+f"(d[1]), "+f"(d[2]), "+f"(d[3])
        : "r"(a.x), "r"(a.y), "r"(a.z), "r"(a.w), "r"(b0), "r"(b1));
}

__device__ __forceinline__ uint32_t packbf(float a, float b) {
    unsigned short ua = __bfloat16_as_ushort(__float2bfloat16(a));
    unsigned short ub = __bfloat16_as_ushort(__float2bfloat16(b));
    return (uint32_t)ua | ((uint32_t)ub << 16);
}

// ---------------------------------------------------------------------------
// Init: Wigner 3j real coupling tensors (double) + output zeroing (verified)
// ---------------------------------------------------------------------------
__device__ double dfac(int n) { double r = 1.0; for (int i = 2; i <= n; i++) r *= (double)i; return r; }

__device__ double w3j_entry(int j1, int j2, int j3, int m1, int m2, int m3) {
    if (m1 + m2 + m3 != 0) return 0.0;
    int t1 = j2 - m1 - j3, t2 = j1 + m2 - j3;
    int kmin = 0; if (t1 > kmin) kmin = t1; if (t2 > kmin) kmin = t2;
    int kmax = j1 + j2 - j3;
    if (j1 - m1 < kmax) kmax = j1 - m1;
    if (j2 + m2 < kmax) kmax = j2 + m2;
    double s = 0.0;
    for (int k = kmin; k <= kmax; k++) {
        double d = dfac(k) * dfac(k - t1) * dfac(k - t2) * dfac(j1 + j2 - j3 - k)
                 * dfac(j1 - m1 - k) * dfac(j2 + m2 - k);
        s += ((k & 1) ? -1.0 : 1.0) / d;
    }
    double sign = ((j1 - j2 - m3) & 1) ? -1.0 : 1.0;
    double pref = sign * sqrt(
        dfac(j1 + j2 - j3) * dfac(j1 - j2 + j3) * dfac(-j1 + j2 + j3) / dfac(j1 + j2 + j3 + 1)
        * dfac(j1 + m1) * dfac(j1 - m1) * dfac(j2 + m2) * dfac(j2 - m2)
        * dfac(j3 + m3) * dfac(j3 - m3));
    return pref * s;
}

__device__ void buildU(int l, double Ur[9][9], double Ui[9][9]) {
    for (int a = 0; a < 9; a++)
        for (int b = 0; b < 9; b++) { Ur[a][b] = 0.0; Ui[a][b] = 0.0; }
    Ur[l][l] = 1.0;
    const double s = 0.70710678118654752440;
    for (int m = 1; m <= l; m++) {
        Ur[l + m][l + m] = (m & 1) ? -s : s;
        Ur[l + m][l - m] = s;
        Ui[l - m][l - m] = s;
        Ui[l - m][l + m] = (m & 1) ? s : -s;
    }
}

__global__ void init_kernel(float* __restrict__ out, int n) {
    if (blockIdx.x >= 19) {
        int base = (blockIdx.x - 19) * 512 + threadIdx.x * 4;
        if (base + 3 < n) {
            *(float4*)&out[base] = make_float4(0.f, 0.f, 0.f, 0.f);
        } else {
            for (int i = base; i < min(base + 4, n); i++) out[i] = 0.0f;
        }
        return;
    }
    const int ci = blockIdx.x;
    const int lo = c3_lo[ci], li = c3_li[ci], lf = c3_lf[ci];
    const int n1 = 2 * lo + 1, n2 = 2 * li + 1, n3 = 2 * lf + 1;
    const int tid = threadIdx.x;

    __shared__ double wtab[25];
    __shared__ double Tre[225], Tim[225];
    __shared__ int    sUseReal;
    __shared__ double sInv;

    if (tid < n1 * n2) {
        int m1 = tid / n2 - lo;
        int m2 = tid % n2 - li;
        int m3 = -m1 - m2;
        double w = 0.0;
        if (m3 >= -lf && m3 <= lf) w = w3j_entry(lo, li, lf, m1, m2, m3);
        wtab[tid] = w;
    }
    __syncthreads();

    double U1r[9][9], U1i[9][9], U2r[9][9], U2i[9][9], U3r[9][9], U3i[9][9];
    buildU(lo, U1r, U1i);
    buildU(li, U2r, U2i);
    buildU(lf, U3r, U3i);

    const int ntot = n1 * n2 * n3;
    for (int o = tid; o < ntot; o += blockDim.x) {
        int a = o / (n2 * n3);
        int b = (o / n3) % n2;
        int c = o % n3;
        double sre = 0.0, sim = 0.0;
        for (int m = 0; m < n1; m++) {
            for (int nn = 0; nn < n2; nn++) {
                double w = wtab[m * n2 + nn];
                if (w == 0.0) continue;
                int m3 = -(m - lo) - (nn - li);
                int p = m3 + lf;
                double ar = U1r[a][m], ai = U1i[a][m];
                double br = U2r[b][nn], bi = U2i[b][nn];
                double pr = ar * br - ai * bi;
                double pi = ar * bi + ai * br;
                double cr = U3r[c][p], ci3 = U3i[c][p];
                sre += w * (pr * cr - pi * ci3);
                sim += w * (pr * ci3 + pi * cr);
            }
        }
        Tre[o] = sre;
        Tim[o] = sim;
    }
    __syncthreads();

    if (tid == 0) {
        double nr = 0.0, ni = 0.0;
        for (int t = 0; t < ntot; t++) { nr += Tre[t] * Tre[t]; ni += Tim[t] * Tim[t]; }
        int ur = (nr >= ni) ? 1 : 0;
        double nn = sqrt(ur ? nr : ni);
        sUseReal = ur;
        sInv = (nn > 0.0) ? (1.0 / nn) : 1.0;
    }
    __syncthreads();

    const int base = c3_off[ci];
    for (int o = tid; o < ntot; o += blockDim.x) {
        double v = (sUseReal ? Tre[o] : Tim[o]) * sInv;
        g_C3[base + o] = (float)v;
    }
}

// ---------------------------------------------------------------------------
// prep B: W3 -> bf16 hi/lo fragments, fi-permuted column order
// ---------------------------------------------------------------------------
__global__ void prepB_kernel(const float* __restrict__ W3) {
    int idx = blockIdx.x * 256 + threadIdx.x;
    if (idx >= 19 * 8 * 7 * 32) return;
    int lane = idx & 31;
    int r2 = idx >> 5;
    int ks = r2 % 7; r2 /= 7;
    int t = r2 & 7;
    int s = r2 >> 3;
    int col = sub_cb[s] + (t * 8 + (lane >> 2)) * sub_nlf[s] + sub_fi[s];
    int k0 = ks * 16 + ((lane & 3) << 1);
    float w00 = (k0     < HID) ? W3[k0 * RTOT + col]       : 0.f;
    float w01 = (k0 + 1 < HID) ? W3[(k0 + 1) * RTOT + col] : 0.f;
    float w10 = (k0 + 8 < HID) ? W3[(k0 + 8) * RTOT + col] : 0.f;
    float w11 = (k0 + 9 < HID) ? W3[(k0 + 9) * RTOT + col] : 0.f;
    uint4 v;
    v.x = packbf(w00, w01);
    v.y = packbf(w10, w11);
    float l00 = w00 - __bfloat162float(__float2bfloat16(w00));
    float l01 = w01 - __bfloat162float(__float2bfloat16(w01));
    float l10 = w10 - __bfloat162float(__float2bfloat16(w10));
    float l11 = w11 - __bfloat162float(__float2bfloat16(w11));
    v.z = packbf(l00, l01);
    v.w = packbf(l10, l11);
    g_B[idx] = v;
}

// ---------------------------------------------------------------------------
// MLP kernel: radial network -> A fragments (bf16 hi/lo)  (verified core)
// ---------------------------------------------------------------------------
__device__ __forceinline__ float swishf(float x) {
    return 1.679177f * x / (1.0f + expf(-x));
}

__global__ __launch_bounds__(NTHR) void mlp_kernel(
    const float* __restrict__ radii,
    const float* __restrict__ W0,
    const float* __restrict__ W1,
    const float* __restrict__ W2,
    int E)
{
    __shared__ float HT[HID * MTE];
    __shared__ float BT[NBASIS * MTE];
    __shared__ float Rad[MTE];

    const int tid = threadIdx.x;
    const int e0  = blockIdx.x * MTE;

    if (tid < MTE) Rad[tid] = radii[min(e0 + tid, E - 1)];
    __syncthreads();
    if (tid < MTE * NBASIS) {
        int b = tid / MTE, e = tid % MTE;
        float ctr = 0.7f + (float)b * (2.5f / 9.0f);
        float d = (Rad[e] - ctr) * (9.0f / 2.5f);
        BT[b * MTE + e] = expf(-d * d);
    }
    __syncthreads();

    const int u  = tid & 127;
    const int eh = tid >> 7;
    float a[8];

    if (u < HID) {
        #pragma unroll
        for (int ee = 0; ee < 8; ee++) a[ee] = 0.0f;
        #pragma unroll
        for (int k = 0; k < NBASIS; k++) {
            float w = W0[k * HID + u];
            const float* bb = &BT[k * MTE + eh * 8];
            #pragma unroll
            for (int ee = 0; ee < 8; ee++) a[ee] += bb[ee] * w;
        }
        #pragma unroll
        for (int ee = 0; ee < 8; ee++)
            HT[u * MTE + eh * 8 + ee] = swishf(a[ee] * 0.31622776601683794f);
    }
    __syncthreads();

    const float* Wl[2] = { W1, W2 };
    #pragma unroll
    for (int layer = 0; layer < 2; layer++) {
        if (u < HID) {
            #pragma unroll
            for (int ee = 0; ee < 8; ee++) a[ee] = 0.0f;
            float wcur = Wl[layer][u];
            #pragma unroll 4
            for (int k = 0; k < HID; k++) {
                float wnext = (k + 1 < HID) ? Wl[layer][(k + 1) * HID + u] : 0.0f;
                float4 h0 = *(const float4*)&HT[k * MTE + eh * 8];
                float4 h1 = *(const float4*)&HT[k * MTE + eh * 8 + 4];
                a[0] += h0.x * wcur; a[1] += h0.y * wcur;
                a[2] += h0.z * wcur; a[3] += h0.w * wcur;
                a[4] += h1.x * wcur; a[5] += h1.y * wcur;
                a[6] += h1.z * wcur; a[7] += h1.w * wcur;
                wcur = wnext;
            }
        }
        __syncthreads();
        if (u < HID) {
            #pragma unroll
            for (int ee = 0; ee < 8; ee++)
                HT[u * MTE + eh * 8 + ee] = swishf(a[ee] * 0.1f);
        }
        __syncthreads();
    }

    // write A fragments for this 16-edge row-tile (mma m16n8k16 A layout)
    uint32_t* gh = g_Ahi + (size_t)blockIdx.x * 896;
    uint32_t* gl = g_Alo + (size_t)blockIdx.x * 896;
    for (int idx = tid; idx < 896; idx += NTHR) {
        int ks = idx >> 7;
        int rem = idx & 127;
        int lane = rem >> 2, r = rem & 3;
        int row = (lane >> 2) + ((r & 1) << 3);
        int k = ks * 16 + ((r >> 1) << 3) + ((lane & 3) << 1);
        float v0 = (k < HID)     ? HT[k * MTE + row]       : 0.0f;
        float v1 = (k + 1 < HID) ? HT[(k + 1) * MTE + row] : 0.0f;
        gh[idx] = packbf(v0, v1);
        float l0 = v0 - __bfloat162float(__float2bfloat16(v0));
        float l1 = v1 - __bfloat162float(__float2bfloat16(v1));
        gl[idx] = packbf(l0, l1);
    }
}

// ---------------------------------------------------------------------------
// Main kernel: mma.sync GEMM + message epilogue + scatter
// ---------------------------------------------------------------------------
template<int LO, int LI>
__device__ __forceinline__ void do_block(
    float* sR, const float* sF, const float* sRsh, const float* sC3,
    const uint32_t* sAhi, const uint32_t* sAlo,
    int pcb, float norm01, float* msg, int tid)
{
    constexpr int NO = 2 * LO + 1;
    constexpr int NI = 2 * LI + 1;
    constexpr int NLF = 2 * (LO < LI ? LO : LI) + 1;
    constexpr int LFMIN = (LO > LI ? LO - LI : LI - LO);
    constexpr int FOI = (LI == 0 ? 0 : (LI == 1 ? 8 : 32));
    constexpr int MB  = (LO == 0 ? 0 : (LO == 1 ? 4 : 16));

    const int wid = tid >> 5, lane = tid & 31;
    const int g = lane >> 2, q = lane & 3;
    const int e = tid & 127, uh = tid >> 7;

    for (int fi = 0; fi < NLF; fi++) {
        const int sub = pcb + fi;
        float d[8][4];
        #pragma unroll
        for (int t = 0; t < 8; t++) { d[t][0] = d[t][1] = d[t][2] = d[t][3] = 0.f; }

        const uint4* gB = g_B + (size_t)sub * 8 * 7 * 32;
        #pragma unroll
        for (int ks = 0; ks < 7; ks++) {
            uint4 ah = *(const uint4*)(sAhi + ((wid * 7 + ks) * 32 + lane) * 4);
            uint4 al = *(const uint4*)(sAlo + ((wid * 7 + ks) * 32 + lane) * 4);
            #pragma unroll
            for (int t = 0; t < 8; t++) {
                uint4 bb = gB[(t * 7 + ks) * 32 + lane];
                mma_bf16(d[t], ah, bb.x, bb.y);   // hi*hi
                mma_bf16(d[t], ah, bb.z, bb.w);   // hi*blo
                mma_bf16(d[t], al, bb.x, bb.y);   // alo*hi
            }
        }
        // D -> sR
        {
            int r0 = wid * 16 + g;
            #pragma unroll
            for (int t = 0; t < 8; t++) {
                *(float2*)&sR[r0 * RSTR + t * 8 + 2 * q]       = make_float2(d[t][0], d[t][1]);
                *(float2*)&sR[(r0 + 8) * RSTR + t * 8 + 2 * q] = make_float2(d[t][2], d[t][3]);
            }
        }
        __syncthreads();

        // message: thread = (e, uh); 4 u's per thread
        {
            const int lf = LFMIN + fi;
            const int nf = 2 * lf + 1;
            const float* C   = sC3 + c3offL[pcb + fi];
            const float* ysh = sRsh + e * RSHD + lf * lf;
            const float* Fb  = sF + e * 73 + FOI;

            float K[NO][NI];
            #pragma unroll
            for (int o = 0; o < NO; o++)
                #pragma unroll
                for (int i = 0; i < NI; i++) {
                    float kk = 0.0f;
                    #pragma unroll
                    for (int mf = 0; mf < nf; mf++)
                        kk += C[(o * NI + i) * nf + mf] * ysh[mf];
                    K[o][i] = kk;
                }

            float aa[4][NO];
            #pragma unroll
            for (int ul = 0; ul < 4; ul++)
                #pragma unroll
                for (int o = 0; o < NO; o++) aa[ul][o] = 0.0f;

            #pragma unroll
            for (int v = 0; v < 8; v++) {
                float Fv[NI];
                #pragma unroll
                for (int i = 0; i < NI; i++) Fv[i] = Fb[v * NI + i];
                float T[NO];
                #pragma unroll
                for (int o = 0; o < NO; o++) {
                    float t = 0.0f;
                    #pragma unroll
                    for (int i = 0; i < NI; i++) t += K[o][i] * Fv[i];
                    T[o] = t;
                }
                #pragma unroll
                for (int ul = 0; ul < 4; ul++) {
                    float Rv = sR[e * RSTR + (uh * 4 + ul) * 8 + v];
                    #pragma unroll
                    for (int o = 0; o < NO; o++) aa[ul][o] += Rv * T[o];
                }
            }
            #pragma unroll
            for (int ul = 0; ul < 4; ul++)
                #pragma unroll
                for (int o = 0; o < NO; o++)
                    msg[MB + ul * NO + o] += norm01 * aa[ul][o];
        }
        __syncthreads();
    }
}

__global__ __launch_bounds__(NTHR) void main_kernel(
    const float* __restrict__ features,
    const int*   __restrict__ eidx,
    const float* __restrict__ rsh,
    float* __restrict__ out,
    int E)
{
    extern __shared__ char smraw[];
    float* sR   = (float*)smraw;                 // 128*66 floats
    float* sF   = sR + ETILE * RSTR;             // 128*73
    float* sRsh = sF + ETILE * 73;               // 128*25
    float* sC3  = sRsh + ETILE * RSHD;           // 1232 (padded)
    int*   sDst = (int*)(sC3 + 1232);            // 128
    int*   sSrc = sDst + 128;                    // 128
    uint32_t* sAhi = (uint32_t*)(sSrc + 128);    // 7168
    uint32_t* sAlo = sAhi + 7168;                // 7168

    const int tid = threadIdx.x;
    const int e0  = blockIdx.x * ETILE;

    for (int i = tid; i < 1225; i += NTHR) sC3[i] = g_C3[i];
    if (tid < ETILE) {
        int e = min(e0 + tid, E - 1);
        sSrc[tid] = eidx[e];
        sDst[tid] = eidx[E + e];
    }
    // A fragment tiles (linear uint4 copy)
    {
        const uint4* gh = (const uint4*)(g_Ahi + (size_t)blockIdx.x * 7168);
        const uint4* gl = (const uint4*)(g_Alo + (size_t)blockIdx.x * 7168);
        uint4* sh = (uint4*)sAhi;
        uint4* sl = (uint4*)sAlo;
        for (int i = tid; i < 1792; i += NTHR) { sh[i] = gh[i]; sl[i] = gl[i]; }
    }
    __syncthreads();

    for (int f = tid; f < ETILE * FEAT; f += NTHR) {
        int e = f / FEAT, c = f % FEAT;
        sF[e * 73 + c] = features[(size_t)sSrc[e] * FEAT + c];
    }
    for (int f = tid; f < ETILE * RSHD; f += NTHR) {
        int e = f / RSHD, c = f % RSHD;
        sRsh[f] = rsh[(size_t)min(e0 + e, E - 1) * RSHD + c];
    }
    __syncthreads();

    float msg[36];
    #pragma unroll
    for (int i = 0; i < 36; i++) msg[i] = 0.0f;

    const float n0 = sqrtf(12.566370614359172f * 1.0f / 24.0f) * 0.1f;
    const float n1 = sqrtf(12.566370614359172f * 3.0f / 56.0f) * 0.1f;
    const float n2 = sqrtf(12.566370614359172f * 5.0f / 72.0f) * 0.1f;

    do_block<0, 0>(sR, sF, sRsh, sC3, sAhi, sAlo,  0, n0, msg, tid);
    do_block<0, 1>(sR, sF, sRsh, sC3, sAhi, sAlo,  1, n0, msg, tid);
    do_block<0, 2>(sR, sF, sRsh, sC3, sAhi, sAlo,  2, n0, msg, tid);
    do_block<1, 0>(sR, sF, sRsh, sC3, sAhi, sAlo,  3, n1, msg, tid);
    do_block<1, 1>(sR, sF, sRsh, sC3, sAhi, sAlo,  4, n1, msg, tid);
    do_block<1, 2>(sR, sF, sRsh, sC3, sAhi, sAlo,  7, n1, msg, tid);
    do_block<2, 0>(sR, sF, sRsh, sC3, sAhi, sAlo, 10, n2, msg, tid);
    do_block<2, 1>(sR, sF, sRsh, sC3, sAhi, sAlo, 11, n2, msg, tid);
    do_block<2, 2>(sR, sF, sRsh, sC3, sAhi, sAlo, 14, n2, msg, tid);

    // scatter: thread (e, uh) adds its 4 u's across the three lo blocks
    const int e = tid & 127, uh = tid >> 7;
    if (e0 + e < E) {
        float* orow = out + (size_t)sDst[e] * FEAT;
        #pragma unroll
        for (int ul = 0; ul < 4; ul++)
            atomicAdd(&orow[uh * 4 + ul], msg[ul]);
        #pragma unroll
        for (int ul = 0; ul < 4; ul++)
            #pragma unroll
            for (int o = 0; o < 3; o++)
                atomicAdd(&orow[8 + (uh * 4 + ul) * 3 + o], msg[4 + ul * 3 + o]);
        #pragma unroll
        for (int ul = 0; ul < 4; ul++)
            #pragma unroll
            for (int o = 0; o < 5; o++)
                atomicAdd(&orow[32 + (uh * 4 + ul) * 5 + o], msg[16 + ul * 5 + o]);
    }
}

// ---------------------------------------------------------------------------
// Launch
// ---------------------------------------------------------------------------
#define SMEM_MAIN ((ETILE*RSTR + ETILE*73 + ETILE*RSHD + 1232) * 4 + 256 * 4 + 14336 * 4)

extern "C" void kernel_launch(void* const* d_in, const int* in_sizes, int n_in,
                              void* d_out, int out_size) {
    const float* features = (const float*)d_in[0];
    const int*   eidx     = (const int*)  d_in[1];
    const float* radii    = (const float*)d_in[2];
    const float* rsh      = (const float*)d_in[3];
    const float* W0       = (const float*)d_in[4];
    const float* W1       = (const float*)d_in[5];
    const float* W2       = (const float*)d_in[6];
    const float* W3       = (const float*)d_in[7];
    float* out = (float*)d_out;

    const int E = in_sizes[2];

    static bool attr_set = false;
    if (!attr_set) {
        cudaFuncSetAttribute(main_kernel,
                             cudaFuncAttributeMaxDynamicSharedMemorySize, SMEM_MAIN);
        attr_set = true;
    }

    const int zblocks = (out_size + 511) / 512;
    init_kernel<<<19 + zblocks, 128>>>(out, out_size);

    prepB_kernel<<<(19 * 8 * 7 * 32 + 255) / 256, 256>>>(W3);

    const int nb = (E + ETILE - 1) / ETILE;      // 782
    mlp_kernel<<<nb * 8, NTHR>>>(radii, W0, W1, W2, E);

    main_kernel<<<nb, NTHR, SMEM_MAIN>>>(features, eidx, rsh, out, E);
}